// round 7
// baseline (speedup 1.0000x reference)
#include <cuda_runtime.h>
#include <cuda_fp16.h>
#include <cstdint>

#define BATCH 256
#define N_GENES 8192
#define WM 4
#define HID (N_GENES * WM)       // 32768
#define N_TF 1024
#define GPT 64
#define EDGES3 (GPT * WM)        // 256
#define EPS 1e-5f
#define GENES_PER_BLOCK 8

// Scratch: layer-2 output stored TRANSPOSED in fp16: hT[col * BATCH + b]
__device__ __half g_hT[HID * BATCH];

__device__ __forceinline__ float2 warp_sum2(float2 v) {
#pragma unroll
    for (int o = 16; o; o >>= 1) {
        v.x += __shfl_xor_sync(0xffffffffu, v.x, o);
        v.y += __shfl_xor_sync(0xffffffffu, v.y, o);
    }
    return v;
}

struct __align__(8) H22 { __half2 a, b; };

// Fused: layer1 -> relu -> BN -> layer2 -> relu -> BN. One warp per gene.
// Lane owns batches {4L..4L+3} and {128+4L..128+4L+3}. BN1 folded into layer2.
__global__ __launch_bounds__(256) void k_layers12(
    const float* __restrict__ x,    // [BATCH, N_GENES] row-major
    const float* __restrict__ w1, const float* __restrict__ b1,
    const float* __restrict__ w2, const float* __restrict__ b2)
{
    __shared__ float sxT[GENES_PER_BLOCK][260];

    const int g0 = blockIdx.x * GENES_PER_BLOCK;
    const int t = threadIdx.x;
    const int warp = t >> 5;
    const int lane = t & 31;

    // Tile load: thread t = batch row t, 8 genes via 2x LDG.128.
    {
        const float4* xr = reinterpret_cast<const float4*>(x + (size_t)t * N_GENES + g0);
        float4 a = xr[0], b = xr[1];
        sxT[0][t] = a.x; sxT[1][t] = a.y; sxT[2][t] = a.z; sxT[3][t] = a.w;
        sxT[4][t] = b.x; sxT[5][t] = b.y; sxT[6][t] = b.z; sxT[7][t] = b.w;
    }
    __syncthreads();

    const int gi = warp;
    const int g = g0 + gi;

    float w1v[4], b1v[4], b2v[4], w2v[16];
#pragma unroll
    for (int j = 0; j < 4; j++) {
        w1v[j] = w1[4 * g + j];
        b1v[j] = b1[4 * g + j];
        b2v[j] = b2[4 * g + j];
    }
#pragma unroll
    for (int e = 0; e < 16; e++) w2v[e] = w2[16 * g + e];

    // layer1 + relu (raw, pre-BN)
    float h1[2][4][4];
#pragma unroll
    for (int k = 0; k < 2; k++) {
        float4 xv = *reinterpret_cast<const float4*>(&sxT[gi][128 * k + 4 * lane]);
        float xs[4] = {xv.x, xv.y, xv.z, xv.w};
#pragma unroll
        for (int p = 0; p < 4; p++)
#pragma unroll
            for (int j = 0; j < 4; j++)
                h1[k][p][j] = fmaxf(fmaf(w1v[j], xs[p], b1v[j]), 0.0f);
    }

    // BN1 stats per column j, fold into layer2 weights
    float m1[4], inv1[4];
#pragma unroll
    for (int j = 0; j < 4; j++) {
        float2 ss = make_float2(0.f, 0.f);
#pragma unroll
        for (int k = 0; k < 2; k++)
#pragma unroll
            for (int p = 0; p < 4; p++) {
                float h = h1[k][p][j];
                ss.x += h; ss.y += h * h;
            }
        ss = warp_sum2(ss);
        float m = ss.x * (1.0f / BATCH);
        float var = fmaxf(ss.y * (1.0f / BATCH) - m * m, 0.0f);
        m1[j] = m;
        inv1[j] = rsqrtf(var + EPS);
    }
    float w2f[16], b2f[4];
#pragma unroll
    for (int i = 0; i < 4; i++) {
        float bb = b2v[i];
#pragma unroll
        for (int j = 0; j < 4; j++) {
            float wf = w2v[4 * i + j] * inv1[j];
            w2f[4 * i + j] = wf;
            bb -= wf * m1[j];
        }
        b2f[i] = bb;
    }

    // layer2 + relu
    float h2[2][4][4];
#pragma unroll
    for (int k = 0; k < 2; k++)
#pragma unroll
        for (int p = 0; p < 4; p++)
#pragma unroll
            for (int i = 0; i < 4; i++) {
                float acc = b2f[i];
#pragma unroll
                for (int j = 0; j < 4; j++) acc = fmaf(w2f[4 * i + j], h1[k][p][j], acc);
                h2[k][p][i] = fmaxf(acc, 0.0f);
            }

    // BN2 per column i, transposed ST.64 half2 store
#pragma unroll
    for (int i = 0; i < 4; i++) {
        float2 ss = make_float2(0.f, 0.f);
#pragma unroll
        for (int k = 0; k < 2; k++)
#pragma unroll
            for (int p = 0; p < 4; p++) {
                float h = h2[k][p][i];
                ss.x += h; ss.y += h * h;
            }
        ss = warp_sum2(ss);
        float m = ss.x * (1.0f / BATCH);
        float var = fmaxf(ss.y * (1.0f / BATCH) - m * m, 0.0f);
        float inv = rsqrtf(var + EPS);

        __half2* dst = reinterpret_cast<__half2*>(&g_hT[(4 * g + i) * BATCH]);
#pragma unroll
        for (int k = 0; k < 2; k++) {
            H22 hv;
            hv.a = __floats2half2_rn((h2[k][0][i] - m) * inv, (h2[k][1][i] - m) * inv);
            hv.b = __floats2half2_rn((h2[k][2][i] - m) * inv, (h2[k][3][i] - m) * inv);
            *reinterpret_cast<H22*>(&dst[64 * k + 2 * lane]) = hv;
        }
    }
}

// layer3: one block (8 warps) per TF; warp handles 32 edges in 8 chunks of 4.
// All 4 gather LDG.128s of a chunk are issued before any FMA (MLP>=4, and
// full unroll lets ptxas pipeline across chunks). fp32 accumulation.
struct __align__(8) WC { float w; int boff; };

__device__ __forceinline__ void fma8(float* acc, float w, const uint4& v) {
    float2 f0 = __half22float2(*reinterpret_cast<const __half2*>(&v.x));
    float2 f1 = __half22float2(*reinterpret_cast<const __half2*>(&v.y));
    float2 f2 = __half22float2(*reinterpret_cast<const __half2*>(&v.z));
    float2 f3 = __half22float2(*reinterpret_cast<const __half2*>(&v.w));
    acc[0] = fmaf(w, f0.x, acc[0]);
    acc[1] = fmaf(w, f0.y, acc[1]);
    acc[2] = fmaf(w, f1.x, acc[2]);
    acc[3] = fmaf(w, f1.y, acc[3]);
    acc[4] = fmaf(w, f2.x, acc[4]);
    acc[5] = fmaf(w, f2.y, acc[5]);
    acc[6] = fmaf(w, f3.x, acc[6]);
    acc[7] = fmaf(w, f3.y, acc[7]);
}

__global__ __launch_bounds__(256) void k_layer3(
    const float* __restrict__ w3, const float* __restrict__ b3,
    const int* __restrict__ cols3,
    float* __restrict__ out)   // [BATCH, N_TF]
{
    const int tf = blockIdx.x;
    const int t = threadIdx.x;        // 0..255
    const int warp = t >> 5;
    const int lane = t & 31;

    __shared__ WC swc[EDGES3];
    __shared__ float sacc[8][BATCH];      // 8 KB
    __shared__ float2 sred[8];

    swc[t].w    = w3[tf * EDGES3 + t];
    swc[t].boff = cols3[tf * EDGES3 + t] * (BATCH * 2);   // bytes
    __syncthreads();

    const char* hbase = reinterpret_cast<const char*>(g_hT) + lane * 16;
    const int ebase = warp * 32;

    float acc[8];
#pragma unroll
    for (int s = 0; s < 8; s++) acc[s] = 0.f;

#pragma unroll
    for (int c = 0; c < 8; c++) {
        WC a0 = swc[ebase + 4 * c + 0];
        WC a1 = swc[ebase + 4 * c + 1];
        WC a2 = swc[ebase + 4 * c + 2];
        WC a3 = swc[ebase + 4 * c + 3];
        uint4 v0 = *reinterpret_cast<const uint4*>(hbase + a0.boff);
        uint4 v1 = *reinterpret_cast<const uint4*>(hbase + a1.boff);
        uint4 v2 = *reinterpret_cast<const uint4*>(hbase + a2.boff);
        uint4 v3 = *reinterpret_cast<const uint4*>(hbase + a3.boff);
        fma8(acc, a0.w, v0);
        fma8(acc, a1.w, v1);
        fma8(acc, a2.w, v2);
        fma8(acc, a3.w, v3);
    }

    // Park partials: warp's acc[s] is batch 8*lane+s
    *reinterpret_cast<float4*>(&sacc[warp][8 * lane])     = make_float4(acc[0], acc[1], acc[2], acc[3]);
    *reinterpret_cast<float4*>(&sacc[warp][8 * lane + 4]) = make_float4(acc[4], acc[5], acc[6], acc[7]);
    __syncthreads();

    // Thread t owns batch b = t: sum over the 8 warps' partials.
    float z = b3[tf];
#pragma unroll
    for (int w = 0; w < 8; w++) z += sacc[w][t];

    // Single-pass BN over the 256 batch values.
    float2 ss = warp_sum2(make_float2(z, z * z));
    if (lane == 0) sred[warp] = ss;
    __syncthreads();
    float S = 0.f, S2 = 0.f;
#pragma unroll
    for (int i = 0; i < 8; i++) { S += sred[i].x; S2 += sred[i].y; }
    float m = S * (1.0f / BATCH);
    float var = fmaxf(S2 * (1.0f / BATCH) - m * m, 0.0f);
    float inv = rsqrtf(var + EPS);

    out[t * N_TF + tf] = (z - m) * inv;
}

extern "C" void kernel_launch(void* const* d_in, const int* in_sizes, int n_in,
                              void* d_out, int out_size)
{
    const float* x  = (const float*)d_in[0];
    const float* w1 = (const float*)d_in[1];
    const float* b1 = (const float*)d_in[2];
    const float* w2 = (const float*)d_in[3];
    const float* b2 = (const float*)d_in[4];
    const float* w3 = (const float*)d_in[5];
    const float* b3 = (const float*)d_in[6];
    const int* cols3 = (const int*)d_in[12];
    float* out = (float*)d_out;

    k_layers12<<<N_GENES / GENES_PER_BLOCK, 256>>>(x, w1, b1, w2, b2);
    k_layer3<<<N_TF, 256>>>(w3, b3, cols3, out);
}

// round 9
// speedup vs baseline: 1.0253x; 1.0253x over previous
#include <cuda_runtime.h>
#include <cuda_fp16.h>
#include <cstdint>

#define BATCH 256
#define N_GENES 8192
#define WM 4
#define HID (N_GENES * WM)       // 32768
#define N_TF 1024
#define GPT 64
#define EDGES3 (GPT * WM)        // 256
#define EPS 1e-5f
#define GENES_PER_BLOCK 8

// Scratch: layer-2 output stored TRANSPOSED in fp16: hT[col * BATCH + b]
__device__ __half g_hT[HID * BATCH];

__device__ __forceinline__ float2 warp_sum2(float2 v) {
#pragma unroll
    for (int o = 16; o; o >>= 1) {
        v.x += __shfl_xor_sync(0xffffffffu, v.x, o);
        v.y += __shfl_xor_sync(0xffffffffu, v.y, o);
    }
    return v;
}

struct __align__(8) H22 { __half2 a, b; };

// Fused: layer1 -> relu -> BN -> layer2 -> relu -> BN. One warp per gene.
// Lane owns batches {4L..4L+3} and {128+4L..128+4L+3}. BN1 folded into layer2.
__global__ __launch_bounds__(256) void k_layers12(
    const float* __restrict__ x,    // [BATCH, N_GENES] row-major
    const float* __restrict__ w1, const float* __restrict__ b1,
    const float* __restrict__ w2, const float* __restrict__ b2)
{
    __shared__ float sxT[GENES_PER_BLOCK][260];

    const int g0 = blockIdx.x * GENES_PER_BLOCK;
    const int t = threadIdx.x;
    const int warp = t >> 5;
    const int lane = t & 31;

    // Tile load: thread t = batch row t, 8 genes via 2x LDG.128.
    {
        const float4* xr = reinterpret_cast<const float4*>(x + (size_t)t * N_GENES + g0);
        float4 a = xr[0], b = xr[1];
        sxT[0][t] = a.x; sxT[1][t] = a.y; sxT[2][t] = a.z; sxT[3][t] = a.w;
        sxT[4][t] = b.x; sxT[5][t] = b.y; sxT[6][t] = b.z; sxT[7][t] = b.w;
    }
    __syncthreads();

    const int gi = warp;
    const int g = g0 + gi;

    float w1v[4], b1v[4], b2v[4], w2v[16];
#pragma unroll
    for (int j = 0; j < 4; j++) {
        w1v[j] = w1[4 * g + j];
        b1v[j] = b1[4 * g + j];
        b2v[j] = b2[4 * g + j];
    }
#pragma unroll
    for (int e = 0; e < 16; e++) w2v[e] = w2[16 * g + e];

    // layer1 + relu (raw, pre-BN)
    float h1[2][4][4];
#pragma unroll
    for (int k = 0; k < 2; k++) {
        float4 xv = *reinterpret_cast<const float4*>(&sxT[gi][128 * k + 4 * lane]);
        float xs[4] = {xv.x, xv.y, xv.z, xv.w};
#pragma unroll
        for (int p = 0; p < 4; p++)
#pragma unroll
            for (int j = 0; j < 4; j++)
                h1[k][p][j] = fmaxf(fmaf(w1v[j], xs[p], b1v[j]), 0.0f);
    }

    // BN1 stats per column j, fold into layer2 weights
    float m1[4], inv1[4];
#pragma unroll
    for (int j = 0; j < 4; j++) {
        float2 ss = make_float2(0.f, 0.f);
#pragma unroll
        for (int k = 0; k < 2; k++)
#pragma unroll
            for (int p = 0; p < 4; p++) {
                float h = h1[k][p][j];
                ss.x += h; ss.y += h * h;
            }
        ss = warp_sum2(ss);
        float m = ss.x * (1.0f / BATCH);
        float var = fmaxf(ss.y * (1.0f / BATCH) - m * m, 0.0f);
        m1[j] = m;
        inv1[j] = rsqrtf(var + EPS);
    }
    float w2f[16], b2f[4];
#pragma unroll
    for (int i = 0; i < 4; i++) {
        float bb = b2v[i];
#pragma unroll
        for (int j = 0; j < 4; j++) {
            float wf = w2v[4 * i + j] * inv1[j];
            w2f[4 * i + j] = wf;
            bb -= wf * m1[j];
        }
        b2f[i] = bb;
    }

    // layer2 + relu
    float h2[2][4][4];
#pragma unroll
    for (int k = 0; k < 2; k++)
#pragma unroll
        for (int p = 0; p < 4; p++)
#pragma unroll
            for (int i = 0; i < 4; i++) {
                float acc = b2f[i];
#pragma unroll
                for (int j = 0; j < 4; j++) acc = fmaf(w2f[4 * i + j], h1[k][p][j], acc);
                h2[k][p][i] = fmaxf(acc, 0.0f);
            }

    // BN2 per column i, transposed ST.64 half2 store
#pragma unroll
    for (int i = 0; i < 4; i++) {
        float2 ss = make_float2(0.f, 0.f);
#pragma unroll
        for (int k = 0; k < 2; k++)
#pragma unroll
            for (int p = 0; p < 4; p++) {
                float h = h2[k][p][i];
                ss.x += h; ss.y += h * h;
            }
        ss = warp_sum2(ss);
        float m = ss.x * (1.0f / BATCH);
        float var = fmaxf(ss.y * (1.0f / BATCH) - m * m, 0.0f);
        float inv = rsqrtf(var + EPS);

        __half2* dst = reinterpret_cast<__half2*>(&g_hT[(4 * g + i) * BATCH]);
#pragma unroll
        for (int k = 0; k < 2; k++) {
            H22 hv;
            hv.a = __floats2half2_rn((h2[k][0][i] - m) * inv, (h2[k][1][i] - m) * inv);
            hv.b = __floats2half2_rn((h2[k][2][i] - m) * inv, (h2[k][3][i] - m) * inv);
            *reinterpret_cast<H22*>(&dst[64 * k + 2 * lane]) = hv;
        }
    }
}

// layer3: one block (8 warps) per TF; warp handles 32 edges in 8 chunks of 4.
// min-blocks=4 frees the register budget (~64/thread) so the 4 staged LDG.128s
// of a chunk genuinely coexist (MLP=4). __ldcg bypasses L1 (no reuse there).
struct __align__(8) WC { float w; int boff; };

__device__ __forceinline__ void fma8(float* acc, float w, const uint4& v) {
    float2 f0 = __half22float2(*reinterpret_cast<const __half2*>(&v.x));
    float2 f1 = __half22float2(*reinterpret_cast<const __half2*>(&v.y));
    float2 f2 = __half22float2(*reinterpret_cast<const __half2*>(&v.z));
    float2 f3 = __half22float2(*reinterpret_cast<const __half2*>(&v.w));
    acc[0] = fmaf(w, f0.x, acc[0]);
    acc[1] = fmaf(w, f0.y, acc[1]);
    acc[2] = fmaf(w, f1.x, acc[2]);
    acc[3] = fmaf(w, f1.y, acc[3]);
    acc[4] = fmaf(w, f2.x, acc[4]);
    acc[5] = fmaf(w, f2.y, acc[5]);
    acc[6] = fmaf(w, f3.x, acc[6]);
    acc[7] = fmaf(w, f3.y, acc[7]);
}

__global__ __launch_bounds__(256, 4) void k_layer3(
    const float* __restrict__ w3, const float* __restrict__ b3,
    const int* __restrict__ cols3,
    float* __restrict__ out)   // [BATCH, N_TF]
{
    const int tf = blockIdx.x;
    const int t = threadIdx.x;        // 0..255
    const int warp = t >> 5;
    const int lane = t & 31;

    __shared__ WC swc[EDGES3];
    __shared__ float sacc[8][BATCH];      // 8 KB
    __shared__ float2 sred[8];

    swc[t].w    = w3[tf * EDGES3 + t];
    swc[t].boff = cols3[tf * EDGES3 + t] * (BATCH * 2);   // bytes
    __syncthreads();

    const char* hbase = reinterpret_cast<const char*>(g_hT) + lane * 16;
    const int ebase = warp * 32;

    float acc[8];
#pragma unroll
    for (int s = 0; s < 8; s++) acc[s] = 0.f;

#pragma unroll
    for (int c = 0; c < 8; c++) {
        WC a0 = swc[ebase + 4 * c + 0];
        WC a1 = swc[ebase + 4 * c + 1];
        WC a2 = swc[ebase + 4 * c + 2];
        WC a3 = swc[ebase + 4 * c + 3];
        uint4 v0 = __ldcg(reinterpret_cast<const uint4*>(hbase + a0.boff));
        uint4 v1 = __ldcg(reinterpret_cast<const uint4*>(hbase + a1.boff));
        uint4 v2 = __ldcg(reinterpret_cast<const uint4*>(hbase + a2.boff));
        uint4 v3 = __ldcg(reinterpret_cast<const uint4*>(hbase + a3.boff));
        fma8(acc, a0.w, v0);
        fma8(acc, a1.w, v1);
        fma8(acc, a2.w, v2);
        fma8(acc, a3.w, v3);
    }

    // Park partials: warp's acc[s] is batch 8*lane+s
    *reinterpret_cast<float4*>(&sacc[warp][8 * lane])     = make_float4(acc[0], acc[1], acc[2], acc[3]);
    *reinterpret_cast<float4*>(&sacc[warp][8 * lane + 4]) = make_float4(acc[4], acc[5], acc[6], acc[7]);
    __syncthreads();

    // Thread t owns batch b = t: sum over the 8 warps' partials.
    float z = b3[tf];
#pragma unroll
    for (int w = 0; w < 8; w++) z += sacc[w][t];

    // Single-pass BN over the 256 batch values.
    float2 ss = warp_sum2(make_float2(z, z * z));
    if (lane == 0) sred[warp] = ss;
    __syncthreads();
    float S = 0.f, S2 = 0.f;
#pragma unroll
    for (int i = 0; i < 8; i++) { S += sred[i].x; S2 += sred[i].y; }
    float m = S * (1.0f / BATCH);
    float var = fmaxf(S2 * (1.0f / BATCH) - m * m, 0.0f);
    float inv = rsqrtf(var + EPS);

    out[t * N_TF + tf] = (z - m) * inv;
}

extern "C" void kernel_launch(void* const* d_in, const int* in_sizes, int n_in,
                              void* d_out, int out_size)
{
    const float* x  = (const float*)d_in[0];
    const float* w1 = (const float*)d_in[1];
    const float* b1 = (const float*)d_in[2];
    const float* w2 = (const float*)d_in[3];
    const float* b2 = (const float*)d_in[4];
    const float* w3 = (const float*)d_in[5];
    const float* b3 = (const float*)d_in[6];
    const int* cols3 = (const int*)d_in[12];
    float* out = (float*)d_out;

    k_layers12<<<N_GENES / GENES_PER_BLOCK, 256>>>(x, w1, b1, w2, b2);
    k_layer3<<<N_TF, 256>>>(w3, b3, cols3, out);
}

// round 10
// speedup vs baseline: 1.0265x; 1.0013x over previous
#include <cuda_runtime.h>
#include <cuda_fp16.h>
#include <cstdint>

#define BATCH 256
#define N_GENES 8192
#define WM 4
#define HID (N_GENES * WM)       // 32768
#define N_TF 1024
#define GPT 64
#define EDGES3 (GPT * WM)        // 256
#define EPS 1e-5f
#define GENES_PER_BLOCK 8

// Scratch: layer-2 output stored TRANSPOSED in fp16: hT[col * BATCH + b]
__device__ __half g_hT[HID * BATCH];

typedef unsigned long long u64;

// ---- packed fp32x2 ops (Blackwell sm_103a; ptxas never auto-fuses these) ----
__device__ __forceinline__ u64 pk2(float lo, float hi) {
    u64 r; asm("mov.b64 %0, {%1, %2};" : "=l"(r) : "f"(lo), "f"(hi)); return r;
}
__device__ __forceinline__ void upk2(u64 v, float& lo, float& hi) {
    asm("mov.b64 {%0, %1}, %2;" : "=f"(lo), "=f"(hi) : "l"(v));
}
__device__ __forceinline__ u64 fma2(u64 a, u64 b, u64 c) {
    u64 d; asm("fma.rn.f32x2 %0, %1, %2, %3;" : "=l"(d) : "l"(a), "l"(b), "l"(c)); return d;
}
__device__ __forceinline__ u64 add2(u64 a, u64 b) {
    u64 d; asm("add.rn.f32x2 %0, %1, %2;" : "=l"(d) : "l"(a), "l"(b)); return d;
}
__device__ __forceinline__ u64 mul2(u64 a, u64 b) {
    u64 d; asm("mul.rn.f32x2 %0, %1, %2;" : "=l"(d) : "l"(a), "l"(b)); return d;
}
__device__ __forceinline__ u64 relu2(u64 a) {
    float x, y; upk2(a, x, y);
    return pk2(fmaxf(x, 0.f), fmaxf(y, 0.f));
}

__device__ __forceinline__ float2 warp_sum2(float2 v) {
#pragma unroll
    for (int o = 16; o; o >>= 1) {
        v.x += __shfl_xor_sync(0xffffffffu, v.x, o);
        v.y += __shfl_xor_sync(0xffffffffu, v.y, o);
    }
    return v;
}

struct __align__(8) H22 { __half2 a, b; };

// Fused: layer1 -> relu -> BN -> layer2 -> relu -> BN. One warp per gene.
// Lane owns batches {4L..4L+3} and {128+4L..128+4L+3}, processed as f32x2
// pairs (pp=0: +0/+1, pp=1: +2/+3). BN1 folded into layer2 (exact algebra).
__global__ __launch_bounds__(256) void k_layers12(
    const float* __restrict__ x,    // [BATCH, N_GENES] row-major
    const float* __restrict__ w1, const float* __restrict__ b1,
    const float* __restrict__ w2, const float* __restrict__ b2)
{
    __shared__ float sxT[GENES_PER_BLOCK][260];

    const int g0 = blockIdx.x * GENES_PER_BLOCK;
    const int t = threadIdx.x;
    const int warp = t >> 5;
    const int lane = t & 31;

    // Tile load: thread t = batch row t, 8 genes via 2x LDG.128.
    {
        const float4* xr = reinterpret_cast<const float4*>(x + (size_t)t * N_GENES + g0);
        float4 a = xr[0], b = xr[1];
        sxT[0][t] = a.x; sxT[1][t] = a.y; sxT[2][t] = a.z; sxT[3][t] = a.w;
        sxT[4][t] = b.x; sxT[5][t] = b.y; sxT[6][t] = b.z; sxT[7][t] = b.w;
    }
    __syncthreads();

    const int gi = warp;
    const int g = g0 + gi;

    // x pairs: [k][pp]
    u64 xp[2][2];
#pragma unroll
    for (int k = 0; k < 2; k++) {
        float4 xv = *reinterpret_cast<const float4*>(&sxT[gi][128 * k + 4 * lane]);
        xp[k][0] = pk2(xv.x, xv.y);
        xp[k][1] = pk2(xv.z, xv.w);
    }

    u64 w1p[4], b1p[4];
    float b2v[4], w2v[16];
#pragma unroll
    for (int j = 0; j < 4; j++) {
        float wv = w1[4 * g + j], bv = b1[4 * g + j];
        w1p[j] = pk2(wv, wv);
        b1p[j] = pk2(bv, bv);
        b2v[j] = b2[4 * g + j];
    }
#pragma unroll
    for (int e = 0; e < 16; e++) w2v[e] = w2[16 * g + e];

    // layer1 + relu (raw, pre-BN), packed pairs: h1[k][pp][j]
    u64 h1[2][2][4];
#pragma unroll
    for (int k = 0; k < 2; k++)
#pragma unroll
        for (int pp = 0; pp < 2; pp++)
#pragma unroll
            for (int j = 0; j < 4; j++)
                h1[k][pp][j] = relu2(fma2(w1p[j], xp[k][pp], b1p[j]));

    // BN1 stats per column j, fold into layer2 weights
    float m1[4], inv1[4];
#pragma unroll
    for (int j = 0; j < 4; j++) {
        u64 s = add2(add2(h1[0][0][j], h1[0][1][j]), add2(h1[1][0][j], h1[1][1][j]));
        u64 q = mul2(h1[0][0][j], h1[0][0][j]);
        q = fma2(h1[0][1][j], h1[0][1][j], q);
        q = fma2(h1[1][0][j], h1[1][0][j], q);
        q = fma2(h1[1][1][j], h1[1][1][j], q);
        float sx, sy, qx, qy;
        upk2(s, sx, sy); upk2(q, qx, qy);
        float2 ss = warp_sum2(make_float2(sx + sy, qx + qy));
        float m = ss.x * (1.0f / BATCH);
        float var = fmaxf(ss.y * (1.0f / BATCH) - m * m, 0.0f);
        m1[j] = m;
        inv1[j] = rsqrtf(var + EPS);
    }
    u64 w2p[16], b2p[4];
#pragma unroll
    for (int i = 0; i < 4; i++) {
        float bb = b2v[i];
#pragma unroll
        for (int j = 0; j < 4; j++) {
            float wf = w2v[4 * i + j] * inv1[j];
            w2p[4 * i + j] = pk2(wf, wf);
            bb -= wf * m1[j];
        }
        b2p[i] = pk2(bb, bb);
    }

    // layer2 + relu, packed: h2[k][pp][i]
    u64 h2[2][2][4];
#pragma unroll
    for (int k = 0; k < 2; k++)
#pragma unroll
        for (int pp = 0; pp < 2; pp++)
#pragma unroll
            for (int i = 0; i < 4; i++) {
                u64 acc = b2p[i];
#pragma unroll
                for (int j = 0; j < 4; j++) acc = fma2(w2p[4 * i + j], h1[k][pp][j], acc);
                h2[k][pp][i] = relu2(acc);
            }

    // BN2 per column i, normalize packed, transposed ST.64 half2 store
#pragma unroll
    for (int i = 0; i < 4; i++) {
        u64 s = add2(add2(h2[0][0][i], h2[0][1][i]), add2(h2[1][0][i], h2[1][1][i]));
        u64 q = mul2(h2[0][0][i], h2[0][0][i]);
        q = fma2(h2[0][1][i], h2[0][1][i], q);
        q = fma2(h2[1][0][i], h2[1][0][i], q);
        q = fma2(h2[1][1][i], h2[1][1][i], q);
        float sx, sy, qx, qy;
        upk2(s, sx, sy); upk2(q, qx, qy);
        float2 ss = warp_sum2(make_float2(sx + sy, qx + qy));
        float m = ss.x * (1.0f / BATCH);
        float var = fmaxf(ss.y * (1.0f / BATCH) - m * m, 0.0f);
        float inv = rsqrtf(var + EPS);

        u64 inv2 = pk2(inv, inv);
        u64 sh2  = pk2(-m * inv, -m * inv);
        __half2* dst = reinterpret_cast<__half2*>(&g_hT[(4 * g + i) * BATCH]);
#pragma unroll
        for (int k = 0; k < 2; k++) {
            u64 p0 = fma2(h2[k][0][i], inv2, sh2);
            u64 p1 = fma2(h2[k][1][i], inv2, sh2);
            float a0, a1, a2, a3;
            upk2(p0, a0, a1); upk2(p1, a2, a3);
            H22 hv;
            hv.a = __floats2half2_rn(a0, a1);
            hv.b = __floats2half2_rn(a2, a3);
            *reinterpret_cast<H22*>(&dst[64 * k + 2 * lane]) = hv;
        }
    }
}

// layer3 (exact R7 config — best measured 14.9us): one block (8 warps) per TF;
// warp handles 32 edges in 8 chunks of 4 staged LDG.128s. fp32 accumulation.
struct __align__(8) WC { float w; int boff; };

__device__ __forceinline__ void fma8(float* acc, float w, const uint4& v) {
    float2 f0 = __half22float2(*reinterpret_cast<const __half2*>(&v.x));
    float2 f1 = __half22float2(*reinterpret_cast<const __half2*>(&v.y));
    float2 f2 = __half22float2(*reinterpret_cast<const __half2*>(&v.z));
    float2 f3 = __half22float2(*reinterpret_cast<const __half2*>(&v.w));
    acc[0] = fmaf(w, f0.x, acc[0]);
    acc[1] = fmaf(w, f0.y, acc[1]);
    acc[2] = fmaf(w, f1.x, acc[2]);
    acc[3] = fmaf(w, f1.y, acc[3]);
    acc[4] = fmaf(w, f2.x, acc[4]);
    acc[5] = fmaf(w, f2.y, acc[5]);
    acc[6] = fmaf(w, f3.x, acc[6]);
    acc[7] = fmaf(w, f3.y, acc[7]);
}

__global__ __launch_bounds__(256) void k_layer3(
    const float* __restrict__ w3, const float* __restrict__ b3,
    const int* __restrict__ cols3,
    float* __restrict__ out)   // [BATCH, N_TF]
{
    const int tf = blockIdx.x;
    const int t = threadIdx.x;        // 0..255
    const int warp = t >> 5;
    const int lane = t & 31;

    __shared__ WC swc[EDGES3];
    __shared__ float sacc[8][BATCH];      // 8 KB
    __shared__ float2 sred[8];

    swc[t].w    = w3[tf * EDGES3 + t];
    swc[t].boff = cols3[tf * EDGES3 + t] * (BATCH * 2);   // bytes
    __syncthreads();

    const char* hbase = reinterpret_cast<const char*>(g_hT) + lane * 16;
    const int ebase = warp * 32;

    float acc[8];
#pragma unroll
    for (int s = 0; s < 8; s++) acc[s] = 0.f;

#pragma unroll
    for (int c = 0; c < 8; c++) {
        WC a0 = swc[ebase + 4 * c + 0];
        WC a1 = swc[ebase + 4 * c + 1];
        WC a2 = swc[ebase + 4 * c + 2];
        WC a3 = swc[ebase + 4 * c + 3];
        uint4 v0 = *reinterpret_cast<const uint4*>(hbase + a0.boff);
        uint4 v1 = *reinterpret_cast<const uint4*>(hbase + a1.boff);
        uint4 v2 = *reinterpret_cast<const uint4*>(hbase + a2.boff);
        uint4 v3 = *reinterpret_cast<const uint4*>(hbase + a3.boff);
        fma8(acc, a0.w, v0);
        fma8(acc, a1.w, v1);
        fma8(acc, a2.w, v2);
        fma8(acc, a3.w, v3);
    }

    // Park partials: warp's acc[s] is batch 8*lane+s
    *reinterpret_cast<float4*>(&sacc[warp][8 * lane])     = make_float4(acc[0], acc[1], acc[2], acc[3]);
    *reinterpret_cast<float4*>(&sacc[warp][8 * lane + 4]) = make_float4(acc[4], acc[5], acc[6], acc[7]);
    __syncthreads();

    // Thread t owns batch b = t: sum over the 8 warps' partials.
    float z = b3[tf];
#pragma unroll
    for (int w = 0; w < 8; w++) z += sacc[w][t];

    // Single-pass BN over the 256 batch values.
    float2 ss = warp_sum2(make_float2(z, z * z));
    if (lane == 0) sred[warp] = ss;
    __syncthreads();
    float S = 0.f, S2 = 0.f;
#pragma unroll
    for (int i = 0; i < 8; i++) { S += sred[i].x; S2 += sred[i].y; }
    float m = S * (1.0f / BATCH);
    float var = fmaxf(S2 * (1.0f / BATCH) - m * m, 0.0f);
    float inv = rsqrtf(var + EPS);

    out[t * N_TF + tf] = (z - m) * inv;
}

extern "C" void kernel_launch(void* const* d_in, const int* in_sizes, int n_in,
                              void* d_out, int out_size)
{
    const float* x  = (const float*)d_in[0];
    const float* w1 = (const float*)d_in[1];
    const float* b1 = (const float*)d_in[2];
    const float* w2 = (const float*)d_in[3];
    const float* b2 = (const float*)d_in[4];
    const float* w3 = (const float*)d_in[5];
    const float* b3 = (const float*)d_in[6];
    const int* cols3 = (const int*)d_in[12];
    float* out = (float*)d_out;

    k_layers12<<<N_GENES / GENES_PER_BLOCK, 256>>>(x, w1, b1, w2, b2);
    k_layer3<<<N_TF, 256>>>(w3, b3, cols3, out);
}